// round 9
// baseline (speedup 1.0000x reference)
#include <cuda_runtime.h>
#include <math_constants.h>

// Prefix-max (cumulative max) along H for x of shape (B=32, C=1, H=1024, W=1024), fp32.
// Layout: x[(b*H + h)*W + w]. 32768 independent columns (b,w), scan length H=1024.
//
// Zero-barrier streaming design: ONE THREAD PER COLUMN. The running max lives
// in a single register -> no block scan, no smem, no __syncthreads, no phases.
// Adjacent lanes = adjacent columns -> every warp LDG/STG is one full 128B line.
//
// Latency hiding via software pipeline: H split into 64 groups of 16 rows,
// double-buffered in registers (load group g+1 while fmax+storing group g),
// keeping ~16 outstanding 128B warp-loads per warp. 1024 warps total
// (~7/SM), so in-flight bytes/SM ~= 7 * 16 * 128B ~= 14KB, enough to cover
// DRAM latency at ~6TB/s.
//
// Grid: 512 CTAs x 64 threads -> the whole grid is resident in ONE wave
// (512 CTAs << 148 SMs * occupancy cap), no tail-wave quantization.

#define H_DIM 1024
#define W_DIM 1024
#define U 16          // rows per group
#define GROUPS 64     // H_DIM / U

__global__ __launch_bounds__(64, 8)
void cummax_kernel(const float* __restrict__ x, float* __restrict__ out) {
    const int col = blockIdx.x * 64 + threadIdx.x;   // 0..32767
    const int b   = col >> 10;
    const int w   = col & (W_DIM - 1);

    const float* __restrict__ src = x   + b * (H_DIM * W_DIM) + w;
    float*       __restrict__ dst = out + b * (H_DIM * W_DIM) + w;

    float m = -CUDART_INF_F;
    float va[U], vb[U];

    // Prologue: load group 0.
#pragma unroll
    for (int i = 0; i < U; i++) va[i] = src[i * W_DIM];

#pragma unroll 1
    for (int gp = 0; gp < GROUPS / 2 - 1; ++gp) {
        const int gA = 2 * gp;
        const int gB = 2 * gp + 1;

        // Load group B (next) while A is still in flight / being consumed.
        const float* sB = src + gB * (U * W_DIM);
#pragma unroll
        for (int i = 0; i < U; i++) vb[i] = sB[i * W_DIM];

        // Process + store group A.
        float* dA = dst + gA * (U * W_DIM);
#pragma unroll
        for (int i = 0; i < U; i++) { m = fmaxf(m, va[i]); dA[i * W_DIM] = m; }

        // Load group A+2.
        const float* sA = src + (gA + 2) * (U * W_DIM);
#pragma unroll
        for (int i = 0; i < U; i++) va[i] = sA[i * W_DIM];

        // Process + store group B.
        float* dB = dst + gB * (U * W_DIM);
#pragma unroll
        for (int i = 0; i < U; i++) { m = fmaxf(m, vb[i]); dB[i * W_DIM] = m; }
    }

    // Epilogue: groups 62 and 63 (va already holds group 62).
    {
        const float* sB = src + (GROUPS - 1) * (U * W_DIM);
#pragma unroll
        for (int i = 0; i < U; i++) vb[i] = sB[i * W_DIM];

        float* dA = dst + (GROUPS - 2) * (U * W_DIM);
#pragma unroll
        for (int i = 0; i < U; i++) { m = fmaxf(m, va[i]); dA[i * W_DIM] = m; }

        float* dB = dst + (GROUPS - 1) * (U * W_DIM);
#pragma unroll
        for (int i = 0; i < U; i++) { m = fmaxf(m, vb[i]); dB[i * W_DIM] = m; }
    }
}

extern "C" void kernel_launch(void* const* d_in, const int* in_sizes, int n_in,
                              void* d_out, int out_size) {
    const float* x = (const float*)d_in[0];
    float* out = (float*)d_out;

    const int total_cols = 32 * W_DIM;        // 32768
    const int grid = total_cols / 64;         // 512
    cummax_kernel<<<grid, 64>>>(x, out);
}

// round 10
// speedup vs baseline: 1.1694x; 1.1694x over previous
#include <cuda_runtime.h>
#include <math_constants.h>

// Prefix-max (cumulative max) along H for x of shape (B=32, C=1, H=1024, W=1024), fp32.
// Layout: x[(b*H + h)*W + w]. 32768 independent columns (b,w), scan length H=1024.
//
// Geometry identical to R7 (best ncu time, 92% occ): 512-thread block owns
// 16 consecutive float-columns x full H; grid 2048; 64B warp segments;
// 4 passes of 8 rows/thread (v[8], <=32 regs, 4 CTAs/SM).
// NEW (single variable): streaming cache hints. __ldcs on loads and __stcs
// on stores — the 256MB stream has zero reuse, so evict-first policy keeps
// dead read lines from thrashing L2 against the write stream.

#define H_DIM 1024
#define W_DIM 1024
#define COLS_PER_BLOCK 16
#define CHUNKS 32
#define ROWS_PER_THREAD 8     // per pass
#define PASS_ROWS 256         // CHUNKS * ROWS_PER_THREAD
#define NUM_PASSES 4

__global__ __launch_bounds__(512, 4)
void cummax_kernel(const float* __restrict__ x, float* __restrict__ out) {
    const int tid   = threadIdx.x;
    const int c     = tid & (COLS_PER_BLOCK - 1);   // 0..15
    const int chunk = tid >> 4;                     // 0..31
    const int wid   = tid >> 5;                     // 0..15
    const int lane  = tid & 31;

    const int col = blockIdx.x * COLS_PER_BLOCK + c;  // 1024 % 16 == 0: no b straddle
    const int b   = col >> 10;
    const int w   = col & (W_DIM - 1);

    const int base0 = b * (H_DIM * W_DIM) + w + chunk * ROWS_PER_THREAD * W_DIM;

    __shared__ float s[2][CHUNKS][COLS_PER_BLOCK + 1];   // double buffer, padded

    float carry = -CUDART_INF_F;

#pragma unroll
    for (int p = 0; p < NUM_PASSES; p++) {
        const int buf  = p & 1;
        const int base = base0 + p * PASS_ROWS * W_DIM;
        const float* __restrict__ src = x   + base;
        float*       __restrict__ dst = out + base;

        // Load 8 rows (coalesced; streaming/evict-first).
        float v[ROWS_PER_THREAD];
#pragma unroll
        for (int i = 0; i < ROWS_PER_THREAD; i++) {
            v[i] = __ldcs(src + i * W_DIM);
        }
#pragma unroll
        for (int i = 1; i < ROWS_PER_THREAD; i++) {
            v[i] = fmaxf(v[i], v[i - 1]);
        }

        // Cross-chunk inclusive max-scan of totals via warp shuffles.
        s[buf][chunk][c] = v[ROWS_PER_THREAD - 1];
        __syncthreads();

        // Warp `wid` scans column `wid`: lane = chunk index. 16 warps, 16 cols.
        {
            float t = s[buf][lane][wid];
#pragma unroll
            for (int d = 1; d < 32; d <<= 1) {
                float o = __shfl_up_sync(0xFFFFFFFFu, t, d);
                if (lane >= d) t = fmaxf(t, o);
            }
            s[buf][lane][wid] = t;
        }
        __syncthreads();

        // Exclusive carry: preceding chunks of this pass + previous passes.
        const float excl = (chunk > 0) ? s[buf][chunk - 1][c] : -CUDART_INF_F;
        const float m = fmaxf(carry, excl);

        // Store (streaming/evict-first).
#pragma unroll
        for (int i = 0; i < ROWS_PER_THREAD; i++) {
            __stcs(dst + i * W_DIM, fmaxf(v[i], m));
        }

        carry = fmaxf(carry, s[buf][CHUNKS - 1][c]);
    }
}

extern "C" void kernel_launch(void* const* d_in, const int* in_sizes, int n_in,
                              void* d_out, int out_size) {
    const float* x = (const float*)d_in[0];
    float* out = (float*)d_out;

    const int total_cols = 32 * W_DIM;                        // 32768
    const int grid = total_cols / COLS_PER_BLOCK;             // 2048
    cummax_kernel<<<grid, 512>>>(x, out);
}

// round 11
// speedup vs baseline: 1.2072x; 1.0323x over previous
#include <cuda_runtime.h>
#include <math_constants.h>

// Prefix-max (cumulative max) along H for x of shape (B=32, C=1, H=1024, W=1024), fp32.
// Layout: x[(b*H + h)*W + w]. As float2: W2=512 f2 per row, 16384 f2-columns.
//
// Geometry = R7/R8 winner, elements widened to float2 (halves LDG/STG count,
// keeps 64B warp segments and grid 2048):
//   256-thread block owns 8 f2-columns (16 float cols) x full H.
//   thread t: c = t & 7 (f2-col), chunk = t >> 3 (32 chunks).
//   4 passes of 8 f2-rows/thread. Per pass: coalesced f2 loads (lanes 0-7 =
//   64B contiguous), componentwise prefix-max, f2 chunk totals -> smem
//   (1 barrier), warp-per-f2-column shuffle scan (5 x 64-bit shfl rounds,
//   no barrier), read-back (1 barrier), apply carry, coalesced f2 stores.
// Double-buffered smem; default cache policy (streaming hints regressed in R10).

#define H_DIM 1024
#define W2_DIM 512            // 1024 floats / 2
#define COLS2_PER_BLOCK 8
#define CHUNKS 32
#define ROWS_PER_THREAD 8     // f2 rows per pass
#define PASS_ROWS 256         // CHUNKS * ROWS_PER_THREAD
#define NUM_PASSES 4

__device__ __forceinline__ float2 fmax2(float2 a, float2 b) {
    return make_float2(fmaxf(a.x, b.x), fmaxf(a.y, b.y));
}

__global__ __launch_bounds__(256, 6)
void cummax_kernel(const float2* __restrict__ x, float2* __restrict__ out) {
    const int tid   = threadIdx.x;
    const int c     = tid & (COLS2_PER_BLOCK - 1);  // 0..7
    const int chunk = tid >> 3;                     // 0..31
    const int wid   = tid >> 5;                     // 0..7
    const int lane  = tid & 31;

    const int col2 = blockIdx.x * COLS2_PER_BLOCK + c;  // 0..16383 (512 % 8 == 0: no b straddle)
    const int b    = col2 >> 9;
    const int w2   = col2 & (W2_DIM - 1);

    const int base0 = b * (H_DIM * W2_DIM) + w2 + chunk * ROWS_PER_THREAD * W2_DIM;

    __shared__ float2 s[2][CHUNKS][COLS2_PER_BLOCK + 1];   // double buffer, 8B pad

    const float2 NEG = make_float2(-CUDART_INF_F, -CUDART_INF_F);
    float2 carry = NEG;

#pragma unroll
    for (int p = 0; p < NUM_PASSES; p++) {
        const int buf  = p & 1;
        const int base = base0 + p * PASS_ROWS * W2_DIM;
        const float2* __restrict__ src = x   + base;
        float2*       __restrict__ dst = out + base;

        // Load 8 f2-rows (lanes 0-7 cover one 64B fully-used segment).
        float2 v[ROWS_PER_THREAD];
#pragma unroll
        for (int i = 0; i < ROWS_PER_THREAD; i++) {
            v[i] = src[i * W2_DIM];
        }
#pragma unroll
        for (int i = 1; i < ROWS_PER_THREAD; i++) {
            v[i] = fmax2(v[i], v[i - 1]);
        }

        // Cross-chunk inclusive max-scan of f2 totals via 64-bit warp shuffles.
        s[buf][chunk][c] = v[ROWS_PER_THREAD - 1];
        __syncthreads();

        // Warp `wid` scans f2-column `wid`: lane = chunk index. 8 warps, 8 f2-cols.
        {
            float2 t = s[buf][lane][wid];
#pragma unroll
            for (int d = 1; d < 32; d <<= 1) {
                double packed;
                // reinterpret float2 <-> double for a single 64-bit shuffle
                packed = __shfl_up_sync(0xFFFFFFFFu,
                                        __longlong_as_double(
                                            (((unsigned long long)__float_as_uint(t.y)) << 32) |
                                            (unsigned long long)__float_as_uint(t.x)),
                                        d);
                unsigned long long up = (unsigned long long)__double_as_longlong(packed);
                float2 o = make_float2(__uint_as_float((unsigned)(up & 0xFFFFFFFFull)),
                                       __uint_as_float((unsigned)(up >> 32)));
                if (lane >= d) t = fmax2(t, o);
            }
            s[buf][lane][wid] = t;
        }
        __syncthreads();

        // Exclusive carry: preceding chunks of this pass + previous passes.
        const float2 excl = (chunk > 0) ? s[buf][chunk - 1][c] : NEG;
        const float2 m = fmax2(carry, excl);

#pragma unroll
        for (int i = 0; i < ROWS_PER_THREAD; i++) {
            dst[i * W2_DIM] = fmax2(v[i], m);
        }

        carry = fmax2(carry, s[buf][CHUNKS - 1][c]);
    }
}

extern "C" void kernel_launch(void* const* d_in, const int* in_sizes, int n_in,
                              void* d_out, int out_size) {
    const float2* x = (const float2*)d_in[0];
    float2* out = (float2*)d_out;

    const int total_cols2 = 32 * W2_DIM;                      // 16384
    const int grid = total_cols2 / COLS2_PER_BLOCK;           // 2048
    cummax_kernel<<<grid, 256>>>(x, out);
}